// round 8
// baseline (speedup 1.0000x reference)
#include <cuda_runtime.h>
#include <cuda_bf16.h>
#include <mma.h>
#include <cstdint>

using namespace nvcuda;
typedef __nv_bfloat16 bf16;
typedef unsigned int u32;

#define TOKENS 8192
#define DM 1024
#define NH 16
#define SD 64
#define NS 1024

// ---------------- scratch (static __device__, no allocation) ----------------
__device__ __align__(16) bf16 g_xh[TOKENS * DM];     // x_norm hi
__device__ __align__(16) bf16 g_xl[TOKENS * DM];     // x_norm lo
__device__ __align__(16) bf16 g_qh[TOKENS * DM];     // q hi
__device__ __align__(16) bf16 g_ql[TOKENS * DM];     // q lo
__device__ __align__(16) bf16 g_read[TOKENS * DM];   // routed read (bf16)
__device__ __align__(16) bf16 g_wqh[DM * DM];        // q_w hi
__device__ __align__(16) bf16 g_wql[DM * DM];        // q_w lo
__device__ __align__(16) bf16 g_wo[DM * DM];         // out_w (plain bf16)
__device__ __align__(16) bf16 g_sig[NH * NS * SD];   // ternarized signatures

// ---------------- helpers ----------------------------------------------------
__device__ __forceinline__ void cp16(void* s, const void* g) {
    asm volatile("cp.async.cg.shared.global [%0], [%1], 16;\n"
                 :: "r"((u32)__cvta_generic_to_shared(s)), "l"(g));
}
__device__ __forceinline__ void cp_commit() { asm volatile("cp.async.commit_group;\n"); }
__device__ __forceinline__ void cp_wait0() { asm volatile("cp.async.wait_group 0;\n"); }

__device__ __forceinline__ void mma_bf16(float& c0, float& c1, float& c2, float& c3,
                                         u32 a0, u32 a1, u32 a2, u32 a3,
                                         u32 b0, u32 b1) {
    asm volatile(
        "mma.sync.aligned.m16n8k16.row.col.f32.bf16.bf16.f32 "
        "{%0,%1,%2,%3}, {%4,%5,%6,%7}, {%8,%9}, {%0,%1,%2,%3};\n"
        : "+f"(c0), "+f"(c1), "+f"(c2), "+f"(c3)
        : "r"(a0), "r"(a1), "r"(a2), "r"(a3), "r"(b0), "r"(b1));
}

// order-preserving fp32 -> u32 key transform
__device__ __forceinline__ u32 fkey(float f) {
    u32 b = __float_as_uint(f);
    return b ^ (u32)(((int)b >> 31) | 0x80000000);
}
__device__ __forceinline__ float unkey(u32 u) {
    u32 b = (u & 0x80000000u) ? (u ^ 0x80000000u) : ~u;
    return __uint_as_float(b);
}

// ---------------- convert weights / ternarize signatures --------------------
__global__ void __launch_bounds__(256) convert_kernel(const float* __restrict__ qw,
                                                      const float* __restrict__ ow,
                                                      const float* __restrict__ sig) {
    int i = blockIdx.x * 256 + threadIdx.x;
    const int N = DM * DM;
    if (i < N) {
        float w = qw[i];
        bf16 h = __float2bfloat16(w);
        g_wqh[i] = h;
        g_wql[i] = __float2bfloat16(w - __bfloat162float(h));
    } else if (i < 2 * N) {
        g_wo[i - N] = __float2bfloat16(ow[i - N]);
    } else if (i < 2 * N + NH * NS * SD) {
        float s = sig[i - 2 * N];
        float t = (s > 0.3f) ? 1.0f : ((s < -0.3f) ? -1.0f : 0.0f);
        g_sig[i - 2 * N] = __float2bfloat16(t);
    }
}

// ---------------- layernorm with hi/lo split output -------------------------
__global__ void __launch_bounds__(256) ln_kernel(const float* __restrict__ x,
                                                 const float* __restrict__ gamma,
                                                 const float* __restrict__ beta) {
    int m = blockIdx.x;
    int tid = threadIdx.x;
    const float4 v = reinterpret_cast<const float4*>(x + (size_t)m * DM)[tid];
    float s = v.x + v.y + v.z + v.w;
    float q = v.x * v.x + v.y * v.y + v.z * v.z + v.w * v.w;
#pragma unroll
    for (int o = 16; o; o >>= 1) {
        s += __shfl_xor_sync(0xffffffffu, s, o);
        q += __shfl_xor_sync(0xffffffffu, q, o);
    }
    __shared__ float ss[8], qq[8];
    int w = tid >> 5;
    if ((tid & 31) == 0) { ss[w] = s; qq[w] = q; }
    __syncthreads();
    if (tid == 0) {
        float S = 0.f, Q = 0.f;
        for (int i = 0; i < 8; i++) { S += ss[i]; Q += qq[i]; }
        ss[0] = S; qq[0] = Q;
    }
    __syncthreads();
    float mean = ss[0] * (1.0f / DM);
    float var = qq[0] * (1.0f / DM) - mean * mean;
    float r = rsqrtf(var + 1e-5f);
    const float4 g = reinterpret_cast<const float4*>(gamma)[tid];
    const float4 b = reinterpret_cast<const float4*>(beta)[tid];
    float o0 = (v.x - mean) * r * g.x + b.x;
    float o1 = (v.y - mean) * r * g.y + b.y;
    float o2 = (v.z - mean) * r * g.z + b.z;
    float o3 = (v.w - mean) * r * g.w + b.w;
    size_t base = (size_t)m * DM + tid * 4;
    float oo[4] = {o0, o1, o2, o3};
#pragma unroll
    for (int i = 0; i < 4; i++) {
        bf16 h = __float2bfloat16(oo[i]);
        g_xh[base + i] = h;
        g_xl[base + i] = __float2bfloat16(oo[i] - __bfloat162float(h));
    }
}

// ---------------- split-bf16 q projection (128x128 tile, 512 thr) -----------
// dynamic smem: Ah[2][5120] Al[2][5120] Wh[2][5120] Wl[2][5120] = 81920 B
// epilogue Cs aliased onto Ah (16 warps * 320 floats = 20480 B)
#define QP_SMEM (4 * 2 * 5120 * 2)

__global__ void __launch_bounds__(512, 1) gemm_qproj(const float* __restrict__ qb) {
    extern __shared__ char dyn[];
    bf16* Ah = (bf16*)dyn;                 // [2][5120]
    bf16* Al = Ah + 2 * 5120;              // [2][5120]
    bf16* Wh = Al + 2 * 5120;              // [2][5120]
    bf16* Wl = Wh + 2 * 5120;              // [2][5120]
    float* Cs = (float*)dyn;               // reused after main loop

    int tid = threadIdx.x, warp = tid >> 5, lane = tid & 31;
    int m0 = blockIdx.y * 128, n0 = blockIdx.x * 128;
    int wm = warp & 3, wn = warp >> 2;     // warp tile: rows wm*32, cols wn*32

    wmma::fragment<wmma::accumulator, 16, 16, 16, float> acc[2][2];
#pragma unroll
    for (int i = 0; i < 2; i++)
#pragma unroll
        for (int j = 0; j < 2; j++) wmma::fill_fragment(acc[i][j], 0.0f);

    int row = tid >> 2, v = tid & 3;
#define QP_STAGE(s, kb) do {                                                   \
        size_t a0 = (size_t)(m0 + row) * DM + (kb) + v * 8;                    \
        cp16(Ah + (s) * 5120 + row * 40 + v * 8, g_xh + a0);                   \
        cp16(Al + (s) * 5120 + row * 40 + v * 8, g_xl + a0);                   \
        size_t w0 = (size_t)(n0 + row) * DM + (kb) + v * 8;                    \
        cp16(Wh + (s) * 5120 + row * 40 + v * 8, g_wqh + w0);                  \
        cp16(Wl + (s) * 5120 + row * 40 + v * 8, g_wql + w0);                  \
    } while (0)

    QP_STAGE(0, 0);
    cp_commit();

    for (int kt = 0; kt < 32; kt++) {
        int buf = kt & 1;
        cp_wait0();
        __syncthreads();
        if (kt < 31) {
            QP_STAGE(buf ^ 1, (kt + 1) * 32);
            cp_commit();
        }
        bf16* ah_ = Ah + buf * 5120;
        bf16* al_ = Al + buf * 5120;
        bf16* wh_ = Wh + buf * 5120;
        bf16* wl_ = Wl + buf * 5120;
#pragma unroll
        for (int ks = 0; ks < 2; ks++) {
            wmma::fragment<wmma::matrix_a, 16, 16, 16, bf16, wmma::row_major> fah[2], fal[2];
            wmma::fragment<wmma::matrix_b, 16, 16, 16, bf16, wmma::col_major> fbh[2], fbl[2];
#pragma unroll
            for (int i = 0; i < 2; i++) {
                wmma::load_matrix_sync(fah[i], ah_ + (wm * 32 + i * 16) * 40 + ks * 16, 40);
                wmma::load_matrix_sync(fal[i], al_ + (wm * 32 + i * 16) * 40 + ks * 16, 40);
            }
#pragma unroll
            for (int j = 0; j < 2; j++) {
                wmma::load_matrix_sync(fbh[j], wh_ + (wn * 32 + j * 16) * 40 + ks * 16, 40);
                wmma::load_matrix_sync(fbl[j], wl_ + (wn * 32 + j * 16) * 40 + ks * 16, 40);
            }
#pragma unroll
            for (int i = 0; i < 2; i++)
#pragma unroll
                for (int j = 0; j < 2; j++) {
                    wmma::mma_sync(acc[i][j], fah[i], fbh[j], acc[i][j]);
                    wmma::mma_sync(acc[i][j], fah[i], fbl[j], acc[i][j]);
                    wmma::mma_sync(acc[i][j], fal[i], fbh[j], acc[i][j]);
                }
        }
    }
    __syncthreads();
    // epilogue: fp32 -> (hi, lo) bf16 pair
    float* cs = Cs + warp * 320;
#pragma unroll
    for (int i = 0; i < 2; i++)
#pragma unroll
        for (int j = 0; j < 2; j++) {
            wmma::store_matrix_sync(cs, acc[i][j], 20, wmma::mem_row_major);
            __syncwarp();
            int mb = m0 + wm * 32 + i * 16, nb = n0 + wn * 32 + j * 16;
#pragma unroll
            for (int t = 0; t < 8; t++) {
                int e = t * 32 + lane;
                int r = e >> 4, c = e & 15;
                float val = cs[r * 20 + c] + qb[nb + c];
                bf16 h = __float2bfloat16(val);
                size_t o = (size_t)(mb + r) * DM + nb + c;
                g_qh[o] = h;
                g_ql[o] = __float2bfloat16(val - __bfloat162float(h));
            }
            __syncwarp();
        }
}

// ---------------- fused scores + top-2 + softmax + gather (v4) --------------
// 128-token tiles: each staged signature chunk feeds 2x the MMAs (halved LDS/HMMA).
#define SLDS 72

__global__ void __launch_bounds__(256, 2) scores_kernel(const float* __restrict__ vals,
                                                        const float* __restrict__ temp) {
    __shared__ __align__(16) bf16 SIG[2][64][SLDS];
    __shared__ u32 Mk1[2][128], Mk2[2][128];
    __shared__ float w1s[128], w2s[128];
    __shared__ int i1s[128], i2s[128];

    int tid = threadIdx.x, lane = tid & 31, warp = tid >> 5;
    int tm = warp & 3, tn = warp >> 2;
    int m0 = blockIdx.x * 128, h = blockIdx.y;
    int gid = lane >> 2, tig = lane & 3;

    // hoisted Q A-fragments (hi + lo), 2 row-tiles of 16 per warp
    u32 ah[2][4][4], al[2][4][4];
#pragma unroll
    for (int rt = 0; rt < 2; rt++) {
        size_t r0 = (size_t)(m0 + tm * 32 + rt * 16 + gid) * DM + h * SD + tig * 2;
        size_t r1 = r0 + 8 * DM;
#pragma unroll
        for (int ks = 0; ks < 4; ks++) {
            ah[rt][ks][0] = *(const u32*)(g_qh + r0 + ks * 16);
            ah[rt][ks][1] = *(const u32*)(g_qh + r1 + ks * 16);
            ah[rt][ks][2] = *(const u32*)(g_qh + r0 + ks * 16 + 8);
            ah[rt][ks][3] = *(const u32*)(g_qh + r1 + ks * 16 + 8);
            al[rt][ks][0] = *(const u32*)(g_ql + r0 + ks * 16);
            al[rt][ks][1] = *(const u32*)(g_ql + r1 + ks * 16);
            al[rt][ks][2] = *(const u32*)(g_ql + r0 + ks * 16 + 8);
            al[rt][ks][3] = *(const u32*)(g_ql + r1 + ks * 16 + 8);
        }
    }

    const bf16* sgbase = g_sig + (size_t)h * NS * SD;
    {
        int e0 = tid, e1 = tid + 256;
        cp16(&SIG[0][e0 >> 3][(e0 & 7) * 8], sgbase + (size_t)(e0 >> 3) * SD + (e0 & 7) * 8);
        cp16(&SIG[0][e1 >> 3][(e1 & 7) * 8], sgbase + (size_t)(e1 >> 3) * SD + (e1 & 7) * 8);
        cp_commit();
    }

    // top-2 keys: index = rt*2 + rowhalf
    u32 k1[4] = {0u, 0u, 0u, 0u}, k2[4] = {0u, 0u, 0u, 0u};

#define UPD(r, f, ci) do {                                       \
        u32 _k = (fkey(f) & 0xFFFFFC00u) | (u32)(ci);            \
        u32 _m = min(k1[r], _k);                                 \
        k1[r] = max(k1[r], _k);                                  \
        k2[r] = max(k2[r], _m);                                  \
    } while (0)

    for (int c = 0; c < 16; c++) {
        int buf = c & 1;
        cp_wait0();
        __syncthreads();
        if (c < 15) {
            const bf16* src = sgbase + (size_t)(c + 1) * 64 * SD;
            int e0 = tid, e1 = tid + 256;
            cp16(&SIG[buf ^ 1][e0 >> 3][(e0 & 7) * 8], src + (size_t)(e0 >> 3) * SD + (e0 & 7) * 8);
            cp16(&SIG[buf ^ 1][e1 >> 3][(e1 & 7) * 8], src + (size_t)(e1 >> 3) * SD + (e1 & 7) * 8);
            cp_commit();
        }
        int cbase = c * 64 + tn * 32 + tig * 2;
#pragma unroll
        for (int nt = 0; nt < 4; nt++) {
            const bf16* bp = &SIG[buf][tn * 32 + nt * 8 + gid][tig * 2];
            u32 b0[4], b1[4];
#pragma unroll
            for (int ks = 0; ks < 4; ks++) {
                b0[ks] = *(const u32*)(bp + ks * 16);
                b1[ks] = *(const u32*)(bp + ks * 16 + 8);
            }
            int ci0 = 1023 - (cbase + nt * 8);
#pragma unroll
            for (int rt = 0; rt < 2; rt++) {
                float c0 = 0.f, c1 = 0.f, c2 = 0.f, c3 = 0.f;
#pragma unroll
                for (int ks = 0; ks < 4; ks++) {
                    mma_bf16(c0, c1, c2, c3, ah[rt][ks][0], ah[rt][ks][1],
                             ah[rt][ks][2], ah[rt][ks][3], b0[ks], b1[ks]);
                    mma_bf16(c0, c1, c2, c3, al[rt][ks][0], al[rt][ks][1],
                             al[rt][ks][2], al[rt][ks][3], b0[ks], b1[ks]);
                }
                UPD(rt * 2 + 0, c0, ci0); UPD(rt * 2 + 0, c1, ci0 - 1);
                UPD(rt * 2 + 1, c2, ci0); UPD(rt * 2 + 1, c3, ci0 - 1);
            }
        }
    }

    // merge top-2 across the 4 lanes sharing each row (tig axis)
#pragma unroll
    for (int off = 1; off < 4; off <<= 1) {
#pragma unroll
        for (int r = 0; r < 4; r++) {
            u32 ok1 = __shfl_xor_sync(0xffffffffu, k1[r], off);
            u32 ok2 = __shfl_xor_sync(0xffffffffu, k2[r], off);
            u32 m = min(k1[r], ok1);
            k1[r] = max(k1[r], ok1);
            k2[r] = max(max(k2[r], ok2), m);
        }
    }
    if (tig == 0) {
#pragma unroll
        for (int rt = 0; rt < 2; rt++) {
            int r = tm * 32 + rt * 16 + gid;
            Mk1[tn][r] = k1[rt * 2 + 0]; Mk2[tn][r] = k2[rt * 2 + 0];
            Mk1[tn][r + 8] = k1[rt * 2 + 1]; Mk2[tn][r + 8] = k2[rt * 2 + 1];
        }
    }
    __syncthreads();

    if (tid < 128) {
        u32 a1 = Mk1[0][tid], a2 = Mk2[0][tid];
        u32 b1 = Mk1[1][tid], b2 = Mk2[1][tid];
        u32 m = min(a1, b1);
        u32 K1 = max(a1, b1);
        u32 K2 = max(max(a2, b2), m);
        int I1 = 1023 - (int)(K1 & 1023u);
        int I2 = 1023 - (int)(K2 & 1023u);
        float V1 = unkey(K1 & 0xFFFFFC00u);
        float V2 = unkey(K2 & 0xFFFFFC00u);
        float t = temp[0];
        float inv = 1.0f / (t * 8.0f);           // 1/(temperature*sqrt(64))
        float e = expf((V2 - V1) * inv);
        float w1 = 1.0f / (1.0f + e);
        w1s[tid] = w1;
        w2s[tid] = 1.0f - w1;
        i1s[tid] = I1;
        i2s[tid] = I2;
    }
    __syncthreads();

    {   // gather slot values, blend, write bf16 read (2 threads per token)
        int tt = tid >> 1, p = tid & 1;
        const float* V = vals + (size_t)h * NS * SD;
        const float4* r1 = (const float4*)(V + (size_t)i1s[tt] * SD) + p * 8;
        const float4* r2 = (const float4*)(V + (size_t)i2s[tt] * SD) + p * 8;
        float a = w1s[tt], b = w2s[tt];
        bf16* dst = g_read + (size_t)(m0 + tt) * DM + h * SD + p * 32;
#pragma unroll
        for (int j = 0; j < 8; j++) {
            float4 xa = r1[j], xb = r2[j];
            float f0 = a * xa.x + b * xb.x;
            float f1 = a * xa.y + b * xb.y;
            float f2 = a * xa.z + b * xb.z;
            float f3 = a * xa.w + b * xb.w;
            ((__nv_bfloat162*)(dst + j * 4))[0] = __floats2bfloat162_rn(f0, f1);
            ((__nv_bfloat162*)(dst + j * 4))[1] = __floats2bfloat162_rn(f2, f3);
        }
    }
}

// ---------------- out projection (128x128 tile, 512 thr) --------------------
__global__ void __launch_bounds__(512, 1) gemm_out(const float* __restrict__ ob,
                                                   const float* __restrict__ x,
                                                   float* __restrict__ out) {
    __shared__ __align__(16) char sraw[2 * 5120 * 2 * 2];   // 40960 B
    bf16* As = (bf16*)sraw;                // [2][5120]
    bf16* Ws = As + 2 * 5120;              // [2][5120]
    float* Cs = (float*)sraw;              // reused after main loop

    int tid = threadIdx.x, warp = tid >> 5, lane = tid & 31;
    int m0 = blockIdx.y * 128, n0 = blockIdx.x * 128;
    int wm = warp & 3, wn = warp >> 2;

    wmma::fragment<wmma::accumulator, 16, 16, 16, float> acc[2][2];
#pragma unroll
    for (int i = 0; i < 2; i++)
#pragma unroll
        for (int j = 0; j < 2; j++) wmma::fill_fragment(acc[i][j], 0.0f);

    int row = tid >> 2, v = tid & 3;
#define GO_STAGE(s, kb) do {                                                   \
        size_t a0 = (size_t)(m0 + row) * DM + (kb) + v * 8;                    \
        cp16(As + (s) * 5120 + row * 40 + v * 8, g_read + a0);                 \
        size_t w0 = (size_t)(n0 + row) * DM + (kb) + v * 8;                    \
        cp16(Ws + (s) * 5120 + row * 40 + v * 8, g_wo + w0);                   \
    } while (0)

    GO_STAGE(0, 0);
    cp_commit();

    for (int kt = 0; kt < 32; kt++) {
        int buf = kt & 1;
        cp_wait0();
        __syncthreads();
        if (kt < 31) {
            GO_STAGE(buf ^ 1, (kt + 1) * 32);
            cp_commit();
        }
        bf16* as_ = As + buf * 5120;
        bf16* ws_ = Ws + buf * 5120;
#pragma unroll
        for (int ks = 0; ks < 2; ks++) {
            wmma::fragment<wmma::matrix_a, 16, 16, 16, bf16, wmma::row_major> af[2];
            wmma::fragment<wmma::matrix_b, 16, 16, 16, bf16, wmma::col_major> bf_[2];
#pragma unroll
            for (int i = 0; i < 2; i++)
                wmma::load_matrix_sync(af[i], as_ + (wm * 32 + i * 16) * 40 + ks * 16, 40);
#pragma unroll
            for (int j = 0; j < 2; j++)
                wmma::load_matrix_sync(bf_[j], ws_ + (wn * 32 + j * 16) * 40 + ks * 16, 40);
#pragma unroll
            for (int i = 0; i < 2; i++)
#pragma unroll
                for (int j = 0; j < 2; j++)
                    wmma::mma_sync(acc[i][j], af[i], bf_[j], acc[i][j]);
        }
    }
    __syncthreads();
    float* cs = Cs + warp * 320;
#pragma unroll
    for (int i = 0; i < 2; i++)
#pragma unroll
        for (int j = 0; j < 2; j++) {
            wmma::store_matrix_sync(cs, acc[i][j], 20, wmma::mem_row_major);
            __syncwarp();
            int mb = m0 + wm * 32 + i * 16, nb = n0 + wn * 32 + j * 16;
#pragma unroll
            for (int t = 0; t < 8; t++) {
                int e = t * 32 + lane;
                int r = e >> 4, c = e & 15;
                size_t o = (size_t)(mb + r) * DM + nb + c;
                out[o] = cs[r * 20 + c] + ob[nb + c] + x[o];
            }
            __syncwarp();
        }
}

// ---------------- launch ----------------------------------------------------
extern "C" void kernel_launch(void* const* d_in, const int* in_sizes, int n_in,
                              void* d_out, int out_size) {
    const float* x = (const float*)d_in[0];
    const float* gamma = (const float*)d_in[1];
    const float* beta = (const float*)d_in[2];
    const float* qw = (const float*)d_in[3];
    const float* qb = (const float*)d_in[4];
    const float* sig = (const float*)d_in[5];
    const float* vals = (const float*)d_in[6];
    const float* ow = (const float*)d_in[7];
    const float* ob = (const float*)d_in[8];
    const float* temp = (const float*)d_in[9];
    float* out = (float*)d_out;

    cudaFuncSetAttribute(gemm_qproj, cudaFuncAttributeMaxDynamicSharedMemorySize, QP_SMEM);

    convert_kernel<<<(3 * DM * DM) / 256, 256>>>(qw, ow, sig);
    ln_kernel<<<TOKENS, 256>>>(x, gamma, beta);
    gemm_qproj<<<dim3(DM / 128, TOKENS / 128), 512, QP_SMEM>>>(qb);
    scores_kernel<<<dim3(TOKENS / 128, NH), 256>>>(vals, temp);
    gemm_out<<<dim3(DM / 128, TOKENS / 128), 512>>>(ob, x, out);
}

// round 9
// speedup vs baseline: 1.1407x; 1.1407x over previous
#include <cuda_runtime.h>
#include <cuda_bf16.h>
#include <mma.h>
#include <cstdint>

using namespace nvcuda;
typedef __nv_bfloat16 bf16;
typedef unsigned int u32;

#define TOKENS 8192
#define DM 1024
#define NH 16
#define SD 64
#define NS 1024

// ---------------- scratch (static __device__, no allocation) ----------------
__device__ __align__(16) bf16 g_xh[TOKENS * DM];     // x_norm hi
__device__ __align__(16) bf16 g_xl[TOKENS * DM];     // x_norm lo
__device__ __align__(16) bf16 g_qh[TOKENS * DM];     // q hi
__device__ __align__(16) bf16 g_ql[TOKENS * DM];     // q lo
__device__ __align__(16) bf16 g_read[TOKENS * DM];   // routed read (bf16)
__device__ __align__(16) bf16 g_wqh[DM * DM];        // q_w hi
__device__ __align__(16) bf16 g_wql[DM * DM];        // q_w lo
__device__ __align__(16) bf16 g_wo[DM * DM];         // out_w (plain bf16)
__device__ __align__(16) bf16 g_sig[NH * NS * SD];   // ternarized signatures

// ---------------- helpers ----------------------------------------------------
__device__ __forceinline__ void cp16(void* s, const void* g) {
    asm volatile("cp.async.cg.shared.global [%0], [%1], 16;\n"
                 :: "r"((u32)__cvta_generic_to_shared(s)), "l"(g));
}
__device__ __forceinline__ void cp_commit() { asm volatile("cp.async.commit_group;\n"); }
__device__ __forceinline__ void cp_wait0() { asm volatile("cp.async.wait_group 0;\n"); }
__device__ __forceinline__ void cp_wait1() { asm volatile("cp.async.wait_group 1;\n"); }

__device__ __forceinline__ void mma_bf16(float& c0, float& c1, float& c2, float& c3,
                                         u32 a0, u32 a1, u32 a2, u32 a3,
                                         u32 b0, u32 b1) {
    asm volatile(
        "mma.sync.aligned.m16n8k16.row.col.f32.bf16.bf16.f32 "
        "{%0,%1,%2,%3}, {%4,%5,%6,%7}, {%8,%9}, {%0,%1,%2,%3};\n"
        : "+f"(c0), "+f"(c1), "+f"(c2), "+f"(c3)
        : "r"(a0), "r"(a1), "r"(a2), "r"(a3), "r"(b0), "r"(b1));
}

// order-preserving fp32 -> u32 key transform
__device__ __forceinline__ u32 fkey(float f) {
    u32 b = __float_as_uint(f);
    return b ^ (u32)(((int)b >> 31) | 0x80000000);
}
__device__ __forceinline__ float unkey(u32 u) {
    u32 b = (u & 0x80000000u) ? (u ^ 0x80000000u) : ~u;
    return __uint_as_float(b);
}

// ---------------- convert weights / ternarize signatures --------------------
__global__ void __launch_bounds__(256) convert_kernel(const float* __restrict__ qw,
                                                      const float* __restrict__ ow,
                                                      const float* __restrict__ sig) {
    int i = blockIdx.x * 256 + threadIdx.x;
    const int N = DM * DM;
    if (i < N) {
        float w = qw[i];
        bf16 h = __float2bfloat16(w);
        g_wqh[i] = h;
        g_wql[i] = __float2bfloat16(w - __bfloat162float(h));
    } else if (i < 2 * N) {
        g_wo[i - N] = __float2bfloat16(ow[i - N]);
    } else if (i < 2 * N + NH * NS * SD) {
        float s = sig[i - 2 * N];
        float t = (s > 0.3f) ? 1.0f : ((s < -0.3f) ? -1.0f : 0.0f);
        g_sig[i - 2 * N] = __float2bfloat16(t);
    }
}

// ---------------- layernorm with hi/lo split output -------------------------
__global__ void __launch_bounds__(256) ln_kernel(const float* __restrict__ x,
                                                 const float* __restrict__ gamma,
                                                 const float* __restrict__ beta) {
    int m = blockIdx.x;
    int tid = threadIdx.x;
    const float4 v = reinterpret_cast<const float4*>(x + (size_t)m * DM)[tid];
    float s = v.x + v.y + v.z + v.w;
    float q = v.x * v.x + v.y * v.y + v.z * v.z + v.w * v.w;
#pragma unroll
    for (int o = 16; o; o >>= 1) {
        s += __shfl_xor_sync(0xffffffffu, s, o);
        q += __shfl_xor_sync(0xffffffffu, q, o);
    }
    __shared__ float ss[8], qq[8];
    int w = tid >> 5;
    if ((tid & 31) == 0) { ss[w] = s; qq[w] = q; }
    __syncthreads();
    if (tid == 0) {
        float S = 0.f, Q = 0.f;
        for (int i = 0; i < 8; i++) { S += ss[i]; Q += qq[i]; }
        ss[0] = S; qq[0] = Q;
    }
    __syncthreads();
    float mean = ss[0] * (1.0f / DM);
    float var = qq[0] * (1.0f / DM) - mean * mean;
    float r = rsqrtf(var + 1e-5f);
    const float4 g = reinterpret_cast<const float4*>(gamma)[tid];
    const float4 b = reinterpret_cast<const float4*>(beta)[tid];
    float o0 = (v.x - mean) * r * g.x + b.x;
    float o1 = (v.y - mean) * r * g.y + b.y;
    float o2 = (v.z - mean) * r * g.z + b.z;
    float o3 = (v.w - mean) * r * g.w + b.w;
    size_t base = (size_t)m * DM + tid * 4;
    float oo[4] = {o0, o1, o2, o3};
#pragma unroll
    for (int i = 0; i < 4; i++) {
        bf16 h = __float2bfloat16(oo[i]);
        g_xh[base + i] = h;
        g_xl[base + i] = __float2bfloat16(oo[i] - __bfloat162float(h));
    }
}

// ---------------- split-bf16 q projection (128x64 tile, 3-stage pipeline) ----
// dynamic smem: 3 stages x (Ah 5120 + Al 5120 + Wh 2560 + Wl 2560) bf16 = 92160 B
// epilogue Cs aliased onto stage buffers.
#define QP_SMEM (3 * (5120 + 5120 + 2560 + 2560) * 2)

__global__ void __launch_bounds__(256) gemm_qproj(const float* __restrict__ qb) {
    extern __shared__ char dyn[];
    bf16* Ah = (bf16*)dyn;                 // [3][5120]
    bf16* Al = Ah + 3 * 5120;              // [3][5120]
    bf16* Wh = Al + 3 * 5120;              // [3][2560]
    bf16* Wl = Wh + 3 * 2560;              // [3][2560]
    float* Cs = (float*)dyn;               // reused after main loop

    int tid = threadIdx.x, warp = tid >> 5, lane = tid & 31;
    int m0 = blockIdx.y * 128, n0 = blockIdx.x * 64;
    int wm = warp & 3, wn = warp >> 2;

    wmma::fragment<wmma::accumulator, 16, 16, 16, float> acc[2][2];
#pragma unroll
    for (int i = 0; i < 2; i++)
#pragma unroll
        for (int j = 0; j < 2; j++) wmma::fill_fragment(acc[i][j], 0.0f);

    int rA0 = tid >> 2, rA1 = (tid + 256) >> 2, vA = tid & 3;
#define QP_STAGE(s, kb) do {                                                       \
        size_t a0 = (size_t)(m0 + rA0) * DM + (kb) + vA * 8;                       \
        size_t a1 = (size_t)(m0 + rA1) * DM + (kb) + vA * 8;                       \
        cp16(Ah + (s) * 5120 + rA0 * 40 + vA * 8, g_xh + a0);                      \
        cp16(Ah + (s) * 5120 + rA1 * 40 + vA * 8, g_xh + a1);                      \
        cp16(Al + (s) * 5120 + rA0 * 40 + vA * 8, g_xl + a0);                      \
        cp16(Al + (s) * 5120 + rA1 * 40 + vA * 8, g_xl + a1);                      \
        size_t w0 = (size_t)(n0 + rA0) * DM + (kb) + vA * 8;                       \
        cp16(Wh + (s) * 2560 + rA0 * 40 + vA * 8, g_wqh + w0);                     \
        cp16(Wl + (s) * 2560 + rA0 * 40 + vA * 8, g_wql + w0);                     \
    } while (0)

    QP_STAGE(0, 0);
    cp_commit();
    QP_STAGE(1, 32);
    cp_commit();

    for (int kt = 0; kt < 32; kt++) {
        int buf = kt % 3;
        cp_wait1();                 // drains group for stage kt (empty groups keep count)
        __syncthreads();
        if (kt + 2 < 32) {
            QP_STAGE((kt + 2) % 3, (kt + 2) * 32);
        }
        cp_commit();                // always commit (possibly empty group)
        bf16* ah_ = Ah + buf * 5120;
        bf16* al_ = Al + buf * 5120;
        bf16* wh_ = Wh + buf * 2560;
        bf16* wl_ = Wl + buf * 2560;
#pragma unroll
        for (int ks = 0; ks < 2; ks++) {
            wmma::fragment<wmma::matrix_a, 16, 16, 16, bf16, wmma::row_major> fah[2], fal[2];
            wmma::fragment<wmma::matrix_b, 16, 16, 16, bf16, wmma::col_major> fbh[2], fbl[2];
#pragma unroll
            for (int i = 0; i < 2; i++) {
                wmma::load_matrix_sync(fah[i], ah_ + (wm * 32 + i * 16) * 40 + ks * 16, 40);
                wmma::load_matrix_sync(fal[i], al_ + (wm * 32 + i * 16) * 40 + ks * 16, 40);
            }
#pragma unroll
            for (int j = 0; j < 2; j++) {
                wmma::load_matrix_sync(fbh[j], wh_ + (wn * 32 + j * 16) * 40 + ks * 16, 40);
                wmma::load_matrix_sync(fbl[j], wl_ + (wn * 32 + j * 16) * 40 + ks * 16, 40);
            }
#pragma unroll
            for (int i = 0; i < 2; i++)
#pragma unroll
                for (int j = 0; j < 2; j++) {
                    wmma::mma_sync(acc[i][j], fah[i], fbh[j], acc[i][j]);
                    wmma::mma_sync(acc[i][j], fah[i], fbl[j], acc[i][j]);
                    wmma::mma_sync(acc[i][j], fal[i], fbh[j], acc[i][j]);
                }
        }
    }
    __syncthreads();
    // epilogue: fp32 -> (hi, lo) bf16 pair
    float* cs = Cs + warp * 320;
#pragma unroll
    for (int i = 0; i < 2; i++)
#pragma unroll
        for (int j = 0; j < 2; j++) {
            wmma::store_matrix_sync(cs, acc[i][j], 20, wmma::mem_row_major);
            __syncwarp();
            int mb = m0 + wm * 32 + i * 16, nb = n0 + wn * 32 + j * 16;
#pragma unroll
            for (int t = 0; t < 8; t++) {
                int e = t * 32 + lane;
                int r = e >> 4, c = e & 15;
                float val = cs[r * 20 + c] + qb[nb + c];
                bf16 h = __float2bfloat16(val);
                size_t o = (size_t)(mb + r) * DM + nb + c;
                g_qh[o] = h;
                g_ql[o] = __float2bfloat16(val - __bfloat162float(h));
            }
            __syncwarp();
        }
}

// ---------------- fused scores + top-2 + softmax + gather (R6 version) ------
// Integer-key top-2 (order-preserving transform, idx packed in low 10 bits).
#define SLDS 72

__global__ void __launch_bounds__(256) scores_kernel(const float* __restrict__ vals,
                                                     const float* __restrict__ temp) {
    __shared__ __align__(16) bf16 SIG[2][64][SLDS];
    __shared__ u32 Mk1[2][64], Mk2[2][64];
    __shared__ float w1s[64], w2s[64];
    __shared__ int i1s[64], i2s[64];

    int tid = threadIdx.x, lane = tid & 31, warp = tid >> 5;
    int tm = warp & 3, tn = warp >> 2;
    int m0 = blockIdx.x * 64, h = blockIdx.y;
    int gid = lane >> 2, tig = lane & 3;

    // hoisted Q A-fragments (hi + lo), loaded straight from gmem
    u32 ah[4][4], al[4][4];
    {
        size_t r0 = (size_t)(m0 + tm * 16 + gid) * DM + h * SD + tig * 2;
        size_t r1 = r0 + 8 * DM;
#pragma unroll
        for (int ks = 0; ks < 4; ks++) {
            ah[ks][0] = *(const u32*)(g_qh + r0 + ks * 16);
            ah[ks][1] = *(const u32*)(g_qh + r1 + ks * 16);
            ah[ks][2] = *(const u32*)(g_qh + r0 + ks * 16 + 8);
            ah[ks][3] = *(const u32*)(g_qh + r1 + ks * 16 + 8);
            al[ks][0] = *(const u32*)(g_ql + r0 + ks * 16);
            al[ks][1] = *(const u32*)(g_ql + r1 + ks * 16);
            al[ks][2] = *(const u32*)(g_ql + r0 + ks * 16 + 8);
            al[ks][3] = *(const u32*)(g_ql + r1 + ks * 16 + 8);
        }
    }

    const bf16* sgbase = g_sig + (size_t)h * NS * SD;
    {
        int e0 = tid, e1 = tid + 256;
        cp16(&SIG[0][e0 >> 3][(e0 & 7) * 8], sgbase + (size_t)(e0 >> 3) * SD + (e0 & 7) * 8);
        cp16(&SIG[0][e1 >> 3][(e1 & 7) * 8], sgbase + (size_t)(e1 >> 3) * SD + (e1 & 7) * 8);
        cp_commit();
    }

    u32 k1[2] = {0u, 0u}, k2[2] = {0u, 0u};

#define UPD(r, f, ci) do {                                       \
        u32 _k = (fkey(f) & 0xFFFFFC00u) | (u32)(ci);            \
        u32 _m = min(k1[r], _k);                                 \
        k1[r] = max(k1[r], _k);                                  \
        k2[r] = max(k2[r], _m);                                  \
    } while (0)

    for (int c = 0; c < 16; c++) {
        int buf = c & 1;
        cp_wait0();
        __syncthreads();
        if (c < 15) {
            const bf16* src = sgbase + (size_t)(c + 1) * 64 * SD;
            int e0 = tid, e1 = tid + 256;
            cp16(&SIG[buf ^ 1][e0 >> 3][(e0 & 7) * 8], src + (size_t)(e0 >> 3) * SD + (e0 & 7) * 8);
            cp16(&SIG[buf ^ 1][e1 >> 3][(e1 & 7) * 8], src + (size_t)(e1 >> 3) * SD + (e1 & 7) * 8);
            cp_commit();
        }
        int cbase = c * 64 + tn * 32 + tig * 2;
#pragma unroll
        for (int nt = 0; nt < 4; nt++) {
            float c0 = 0.f, c1 = 0.f, c2 = 0.f, c3 = 0.f;
            const bf16* bp = &SIG[buf][tn * 32 + nt * 8 + gid][tig * 2];
#pragma unroll
            for (int ks = 0; ks < 4; ks++) {
                u32 b0 = *(const u32*)(bp + ks * 16);
                u32 b1 = *(const u32*)(bp + ks * 16 + 8);
                mma_bf16(c0, c1, c2, c3, ah[ks][0], ah[ks][1], ah[ks][2], ah[ks][3], b0, b1);
                mma_bf16(c0, c1, c2, c3, al[ks][0], al[ks][1], al[ks][2], al[ks][3], b0, b1);
            }
            int ci0 = 1023 - (cbase + nt * 8);  // for c0 (row gid) and c2 (row gid+8)
            UPD(0, c0, ci0); UPD(0, c1, ci0 - 1);
            UPD(1, c2, ci0); UPD(1, c3, ci0 - 1);
        }
    }

    // merge top-2 across the 4 lanes sharing each row (tig axis)
#pragma unroll
    for (int off = 1; off < 4; off <<= 1) {
#pragma unroll
        for (int r = 0; r < 2; r++) {
            u32 ok1 = __shfl_xor_sync(0xffffffffu, k1[r], off);
            u32 ok2 = __shfl_xor_sync(0xffffffffu, k2[r], off);
            u32 m = min(k1[r], ok1);
            k1[r] = max(k1[r], ok1);
            k2[r] = max(max(k2[r], ok2), m);
        }
    }
    if (tig == 0) {
        int r = tm * 16 + gid;
        Mk1[tn][r] = k1[0]; Mk2[tn][r] = k2[0];
        Mk1[tn][r + 8] = k1[1]; Mk2[tn][r + 8] = k2[1];
    }
    __syncthreads();

    if (tid < 64) {
        u32 a1 = Mk1[0][tid], a2 = Mk2[0][tid];
        u32 b1 = Mk1[1][tid], b2 = Mk2[1][tid];
        u32 m = min(a1, b1);
        u32 K1 = max(a1, b1);
        u32 K2 = max(max(a2, b2), m);
        int I1 = 1023 - (int)(K1 & 1023u);
        int I2 = 1023 - (int)(K2 & 1023u);
        float V1 = unkey(K1 & 0xFFFFFC00u);
        float V2 = unkey(K2 & 0xFFFFFC00u);
        float t = temp[0];
        float inv = 1.0f / (t * 8.0f);           // 1/(temperature*sqrt(64))
        float e = expf((V2 - V1) * inv);
        float w1 = 1.0f / (1.0f + e);
        w1s[tid] = w1;
        w2s[tid] = 1.0f - w1;
        i1s[tid] = I1;
        i2s[tid] = I2;
    }
    __syncthreads();

    {   // gather slot values, blend, write bf16 read
        int tt = tid >> 2, p = tid & 3;
        const float* V = vals + (size_t)h * NS * SD;
        const float4* r1 = (const float4*)(V + (size_t)i1s[tt] * SD);
        const float4* r2 = (const float4*)(V + (size_t)i2s[tt] * SD);
        float a = w1s[tt], b = w2s[tt];
        bf16* dst = g_read + (size_t)(m0 + tt) * DM + h * SD + p * 16;
#pragma unroll
        for (int j = 0; j < 4; j++) {
            float4 xa = r1[p * 4 + j], xb = r2[p * 4 + j];
            float f0 = a * xa.x + b * xb.x;
            float f1 = a * xa.y + b * xb.y;
            float f2 = a * xa.z + b * xb.z;
            float f3 = a * xa.w + b * xb.w;
            ((__nv_bfloat162*)(dst + j * 4))[0] = __floats2bfloat162_rn(f0, f1);
            ((__nv_bfloat162*)(dst + j * 4))[1] = __floats2bfloat162_rn(f2, f3);
        }
    }
}

// ---------------- out projection (128x64 tile, 3-stage pipeline) ------------
__global__ void __launch_bounds__(256) gemm_out(const float* __restrict__ ob,
                                                const float* __restrict__ x,
                                                float* __restrict__ out) {
    __shared__ __align__(16) char sraw[3 * (5120 + 2560) * 2];   // 46080 B
    bf16* As = (bf16*)sraw;                // [3][5120]
    bf16* Ws = As + 3 * 5120;              // [3][2560]
    float* Cs = (float*)sraw;              // reused after main loop

    int tid = threadIdx.x, warp = tid >> 5, lane = tid & 31;
    int m0 = blockIdx.y * 128, n0 = blockIdx.x * 64;
    int wm = warp & 3, wn = warp >> 2;

    wmma::fragment<wmma::accumulator, 16, 16, 16, float> acc[2][2];
#pragma unroll
    for (int i = 0; i < 2; i++)
#pragma unroll
        for (int j = 0; j < 2; j++) wmma::fill_fragment(acc[i][j], 0.0f);

    int rA0 = tid >> 2, rA1 = (tid + 256) >> 2, vA = tid & 3;
#define GO_STAGE(s, kb) do {                                                   \
        size_t a0 = (size_t)(m0 + rA0) * DM + (kb) + vA * 8;                   \
        size_t a1 = (size_t)(m0 + rA1) * DM + (kb) + vA * 8;                   \
        cp16(As + (s) * 5120 + rA0 * 40 + vA * 8, g_read + a0);                \
        cp16(As + (s) * 5120 + rA1 * 40 + vA * 8, g_read + a1);                \
        size_t w0 = (size_t)(n0 + rA0) * DM + (kb) + vA * 8;                   \
        cp16(Ws + (s) * 2560 + rA0 * 40 + vA * 8, g_wo + w0);                  \
    } while (0)

    GO_STAGE(0, 0);
    cp_commit();
    GO_STAGE(1, 32);
    cp_commit();

    for (int kt = 0; kt < 32; kt++) {
        int buf = kt % 3;
        cp_wait1();
        __syncthreads();
        if (kt + 2 < 32) {
            GO_STAGE((kt + 2) % 3, (kt + 2) * 32);
        }
        cp_commit();
        bf16* as_ = As + buf * 5120;
        bf16* ws_ = Ws + buf * 2560;
#pragma unroll
        for (int ks = 0; ks < 2; ks++) {
            wmma::fragment<wmma::matrix_a, 16, 16, 16, bf16, wmma::row_major> af[2];
            wmma::fragment<wmma::matrix_b, 16, 16, 16, bf16, wmma::col_major> bf_[2];
#pragma unroll
            for (int i = 0; i < 2; i++)
                wmma::load_matrix_sync(af[i], as_ + (wm * 32 + i * 16) * 40 + ks * 16, 40);
#pragma unroll
            for (int j = 0; j < 2; j++)
                wmma::load_matrix_sync(bf_[j], ws_ + (wn * 32 + j * 16) * 40 + ks * 16, 40);
#pragma unroll
            for (int i = 0; i < 2; i++)
#pragma unroll
                for (int j = 0; j < 2; j++)
                    wmma::mma_sync(acc[i][j], af[i], bf_[j], acc[i][j]);
        }
    }
    __syncthreads();
    float* cs = Cs + warp * 320;
#pragma unroll
    for (int i = 0; i < 2; i++)
#pragma unroll
        for (int j = 0; j < 2; j++) {
            wmma::store_matrix_sync(cs, acc[i][j], 20, wmma::mem_row_major);
            __syncwarp();
            int mb = m0 + wm * 32 + i * 16, nb = n0 + wn * 32 + j * 16;
#pragma unroll
            for (int t = 0; t < 8; t++) {
                int e = t * 32 + lane;
                int r = e >> 4, c = e & 15;
                size_t o = (size_t)(mb + r) * DM + nb + c;
                out[o] = cs[r * 20 + c] + ob[nb + c] + x[o];
            }
            __syncwarp();
        }
}

// ---------------- launch ----------------------------------------------------
extern "C" void kernel_launch(void* const* d_in, const int* in_sizes, int n_in,
                              void* d_out, int out_size) {
    const float* x = (const float*)d_in[0];
    const float* gamma = (const float*)d_in[1];
    const float* beta = (const float*)d_in[2];
    const float* qw = (const float*)d_in[3];
    const float* qb = (const float*)d_in[4];
    const float* sig = (const float*)d_in[5];
    const float* vals = (const float*)d_in[6];
    const float* ow = (const float*)d_in[7];
    const float* ob = (const float*)d_in[8];
    const float* temp = (const float*)d_in[9];
    float* out = (float*)d_out;

    cudaFuncSetAttribute(gemm_qproj, cudaFuncAttributeMaxDynamicSharedMemorySize, QP_SMEM);

    convert_kernel<<<(3 * DM * DM) / 256, 256>>>(qw, ow, sig);
    ln_kernel<<<TOKENS, 256>>>(x, gamma, beta);
    gemm_qproj<<<dim3(DM / 64, TOKENS / 128), 256, QP_SMEM>>>(qb);
    scores_kernel<<<dim3(TOKENS / 64, NH), 256>>>(vals, temp);
    gemm_out<<<dim3(DM / 64, TOKENS / 128), 256>>>(ob, x, out);
}

// round 12
// speedup vs baseline: 1.1847x; 1.0385x over previous
#include <cuda_runtime.h>
#include <cuda_bf16.h>
#include <mma.h>
#include <cstdint>

using namespace nvcuda;
typedef __nv_bfloat16 bf16;
typedef unsigned int u32;

#define TOKENS 8192
#define DM 1024
#define NH 16
#define SD 64
#define NS 1024

// ---------------- scratch (static __device__, no allocation) ----------------
__device__ __align__(16) bf16 g_xh[TOKENS * DM];     // x_norm hi
__device__ __align__(16) bf16 g_xl[TOKENS * DM];     // x_norm lo
__device__ __align__(16) bf16 g_qh[TOKENS * DM];     // q hi
__device__ __align__(16) bf16 g_ql[TOKENS * DM];     // q lo
__device__ __align__(16) bf16 g_read[TOKENS * DM];   // routed read (bf16)
__device__ __align__(16) bf16 g_wqh[DM * DM];        // q_w hi
__device__ __align__(16) bf16 g_wql[DM * DM];        // q_w lo
__device__ __align__(16) bf16 g_wo[DM * DM];         // out_w (plain bf16)
__device__ __align__(16) bf16 g_sig[NH * NS * SD];   // ternarized signatures

// ---------------- helpers ----------------------------------------------------
__device__ __forceinline__ void cp16(void* s, const void* g) {
    asm volatile("cp.async.cg.shared.global [%0], [%1], 16;\n"
                 :: "r"((u32)__cvta_generic_to_shared(s)), "l"(g));
}
__device__ __forceinline__ void cp_commit() { asm volatile("cp.async.commit_group;\n"); }
__device__ __forceinline__ void cp_wait0() { asm volatile("cp.async.wait_group 0;\n"); }

__device__ __forceinline__ void mma_bf16(float& c0, float& c1, float& c2, float& c3,
                                         u32 a0, u32 a1, u32 a2, u32 a3,
                                         u32 b0, u32 b1) {
    asm volatile(
        "mma.sync.aligned.m16n8k16.row.col.f32.bf16.bf16.f32 "
        "{%0,%1,%2,%3}, {%4,%5,%6,%7}, {%8,%9}, {%0,%1,%2,%3};\n"
        : "+f"(c0), "+f"(c1), "+f"(c2), "+f"(c3)
        : "r"(a0), "r"(a1), "r"(a2), "r"(a3), "r"(b0), "r"(b1));
}

__device__ __forceinline__ void ldsm_x4(u32& r0, u32& r1, u32& r2, u32& r3, u32 saddr) {
    asm volatile("ldmatrix.sync.aligned.m8n8.x4.shared.b16 {%0,%1,%2,%3}, [%4];\n"
                 : "=r"(r0), "=r"(r1), "=r"(r2), "=r"(r3) : "r"(saddr));
}

// ---------------- convert weights / ternarize signatures --------------------
__global__ void __launch_bounds__(256) convert_kernel(const float* __restrict__ qw,
                                                      const float* __restrict__ ow,
                                                      const float* __restrict__ sig) {
    int i = blockIdx.x * 256 + threadIdx.x;
    const int N = DM * DM;
    if (i < N) {
        float w = qw[i];
        bf16 h = __float2bfloat16(w);
        g_wqh[i] = h;
        g_wql[i] = __float2bfloat16(w - __bfloat162float(h));
    } else if (i < 2 * N) {
        g_wo[i - N] = __float2bfloat16(ow[i - N]);
    } else if (i < 2 * N + NH * NS * SD) {
        float s = sig[i - 2 * N];
        float t = (s > 0.3f) ? 1.0f : ((s < -0.3f) ? -1.0f : 0.0f);
        g_sig[i - 2 * N] = __float2bfloat16(t);
    }
}

// ---------------- layernorm with hi/lo split output -------------------------
__global__ void __launch_bounds__(256) ln_kernel(const float* __restrict__ x,
                                                 const float* __restrict__ gamma,
                                                 const float* __restrict__ beta) {
    int m = blockIdx.x;
    int tid = threadIdx.x;
    const float4 v = reinterpret_cast<const float4*>(x + (size_t)m * DM)[tid];
    float s = v.x + v.y + v.z + v.w;
    float q = v.x * v.x + v.y * v.y + v.z * v.z + v.w * v.w;
#pragma unroll
    for (int o = 16; o; o >>= 1) {
        s += __shfl_xor_sync(0xffffffffu, s, o);
        q += __shfl_xor_sync(0xffffffffu, q, o);
    }
    __shared__ float ss[8], qq[8];
    int w = tid >> 5;
    if ((tid & 31) == 0) { ss[w] = s; qq[w] = q; }
    __syncthreads();
    if (tid == 0) {
        float S = 0.f, Q = 0.f;
        for (int i = 0; i < 8; i++) { S += ss[i]; Q += qq[i]; }
        ss[0] = S; qq[0] = Q;
    }
    __syncthreads();
    float mean = ss[0] * (1.0f / DM);
    float var = qq[0] * (1.0f / DM) - mean * mean;
    float r = rsqrtf(var + 1e-5f);
    const float4 g = reinterpret_cast<const float4*>(gamma)[tid];
    const float4 b = reinterpret_cast<const float4*>(beta)[tid];
    float o0 = (v.x - mean) * r * g.x + b.x;
    float o1 = (v.y - mean) * r * g.y + b.y;
    float o2 = (v.z - mean) * r * g.z + b.z;
    float o3 = (v.w - mean) * r * g.w + b.w;
    size_t base = (size_t)m * DM + tid * 4;
    float oo[4] = {o0, o1, o2, o3};
#pragma unroll
    for (int i = 0; i < 4; i++) {
        bf16 h = __float2bfloat16(oo[i]);
        g_xh[base + i] = h;
        g_xl[base + i] = __float2bfloat16(oo[i] - __bfloat162float(h));
    }
}

// ---------------- split-bf16 q projection (R6: 128x64, 2-stage) -------------
#define QP_SMEM (2*128*40*2*2 + 2*64*40*2*2 + 8*16*20*4)

__global__ void __launch_bounds__(256) gemm_qproj(const float* __restrict__ qb) {
    extern __shared__ char dyn[];
    bf16* Ah = (bf16*)dyn;                 // [2][5120]
    bf16* Al = Ah + 2 * 5120;              // [2][5120]
    bf16* Wh = Al + 2 * 5120;              // [2][2560]
    bf16* Wl = Wh + 2 * 2560;              // [2][2560]
    float* Cs = (float*)(Wl + 2 * 2560);   // [8*16*20]

    int tid = threadIdx.x, warp = tid >> 5, lane = tid & 31;
    int m0 = blockIdx.y * 128, n0 = blockIdx.x * 64;
    int wm = warp & 3, wn = warp >> 2;

    wmma::fragment<wmma::accumulator, 16, 16, 16, float> acc[2][2];
#pragma unroll
    for (int i = 0; i < 2; i++)
#pragma unroll
        for (int j = 0; j < 2; j++) wmma::fill_fragment(acc[i][j], 0.0f);

    int rA0 = tid >> 2, rA1 = (tid + 256) >> 2, vA = tid & 3;
#define QP_STAGE(s, kb) do {                                                       \
        size_t a0 = (size_t)(m0 + rA0) * DM + (kb) + vA * 8;                       \
        size_t a1 = (size_t)(m0 + rA1) * DM + (kb) + vA * 8;                       \
        cp16(Ah + (s) * 5120 + rA0 * 40 + vA * 8, g_xh + a0);                      \
        cp16(Ah + (s) * 5120 + rA1 * 40 + vA * 8, g_xh + a1);                      \
        cp16(Al + (s) * 5120 + rA0 * 40 + vA * 8, g_xl + a0);                      \
        cp16(Al + (s) * 5120 + rA1 * 40 + vA * 8, g_xl + a1);                      \
        size_t w0 = (size_t)(n0 + rA0) * DM + (kb) + vA * 8;                       \
        cp16(Wh + (s) * 2560 + rA0 * 40 + vA * 8, g_wqh + w0);                     \
        cp16(Wl + (s) * 2560 + rA0 * 40 + vA * 8, g_wql + w0);                     \
    } while (0)

    QP_STAGE(0, 0);
    cp_commit();

    for (int kt = 0; kt < 32; kt++) {
        int buf = kt & 1;
        cp_wait0();
        __syncthreads();
        if (kt < 31) {
            QP_STAGE(buf ^ 1, (kt + 1) * 32);
            cp_commit();
        }
        bf16* ah_ = Ah + buf * 5120;
        bf16* al_ = Al + buf * 5120;
        bf16* wh_ = Wh + buf * 2560;
        bf16* wl_ = Wl + buf * 2560;
#pragma unroll
        for (int ks = 0; ks < 2; ks++) {
            wmma::fragment<wmma::matrix_a, 16, 16, 16, bf16, wmma::row_major> fah[2], fal[2];
            wmma::fragment<wmma::matrix_b, 16, 16, 16, bf16, wmma::col_major> fbh[2], fbl[2];
#pragma unroll
            for (int i = 0; i < 2; i++) {
                wmma::load_matrix_sync(fah[i], ah_ + (wm * 32 + i * 16) * 40 + ks * 16, 40);
                wmma::load_matrix_sync(fal[i], al_ + (wm * 32 + i * 16) * 40 + ks * 16, 40);
            }
#pragma unroll
            for (int j = 0; j < 2; j++) {
                wmma::load_matrix_sync(fbh[j], wh_ + (wn * 32 + j * 16) * 40 + ks * 16, 40);
                wmma::load_matrix_sync(fbl[j], wl_ + (wn * 32 + j * 16) * 40 + ks * 16, 40);
            }
#pragma unroll
            for (int i = 0; i < 2; i++)
#pragma unroll
                for (int j = 0; j < 2; j++) {
                    wmma::mma_sync(acc[i][j], fah[i], fbh[j], acc[i][j]);
                    wmma::mma_sync(acc[i][j], fah[i], fbl[j], acc[i][j]);
                    wmma::mma_sync(acc[i][j], fal[i], fbh[j], acc[i][j]);
                }
        }
    }
    __syncthreads();
    float* cs = Cs + warp * 320;
#pragma unroll
    for (int i = 0; i < 2; i++)
#pragma unroll
        for (int j = 0; j < 2; j++) {
            wmma::store_matrix_sync(cs, acc[i][j], 20, wmma::mem_row_major);
            __syncwarp();
            int mb = m0 + wm * 32 + i * 16, nb = n0 + wn * 32 + j * 16;
#pragma unroll
            for (int t = 0; t < 8; t++) {
                int e = t * 32 + lane;
                int r = e >> 4, c = e & 15;
                float val = cs[r * 20 + c] + qb[nb + c];
                bf16 h = __float2bfloat16(val);
                size_t o = (size_t)(mb + r) * DM + nb + c;
                g_qh[o] = h;
                g_ql[o] = __float2bfloat16(val - __bfloat162float(h));
            }
            __syncwarp();
        }
}

// ---------------- fused scores + top-2 + softmax + gather (v5) --------------
// ldmatrix.x4 B-fragments + float-packed top-2 keys (idx in low 10 mantissa bits).
#define SLDS 72

__global__ void __launch_bounds__(256) scores_kernel(const float* __restrict__ vals,
                                                     const float* __restrict__ temp) {
    __shared__ __align__(16) bf16 SIG[2][64][SLDS];
    __shared__ float Mk1[2][64], Mk2[2][64];
    __shared__ float w1s[64], w2s[64];
    __shared__ int i1s[64], i2s[64];

    int tid = threadIdx.x, lane = tid & 31, warp = tid >> 5;
    int tm = warp & 3, tn = warp >> 2;
    int m0 = blockIdx.x * 64, h = blockIdx.y;
    int gid = lane >> 2, tig = lane & 3;

    // hoisted Q A-fragments (hi + lo), loaded straight from gmem
    u32 ah[4][4], al[4][4];
    {
        size_t r0 = (size_t)(m0 + tm * 16 + gid) * DM + h * SD + tig * 2;
        size_t r1 = r0 + 8 * DM;
#pragma unroll
        for (int ks = 0; ks < 4; ks++) {
            ah[ks][0] = *(const u32*)(g_qh + r0 + ks * 16);
            ah[ks][1] = *(const u32*)(g_qh + r1 + ks * 16);
            ah[ks][2] = *(const u32*)(g_qh + r0 + ks * 16 + 8);
            ah[ks][3] = *(const u32*)(g_qh + r1 + ks * 16 + 8);
            al[ks][0] = *(const u32*)(g_ql + r0 + ks * 16);
            al[ks][1] = *(const u32*)(g_ql + r1 + ks * 16);
            al[ks][2] = *(const u32*)(g_ql + r0 + ks * 16 + 8);
            al[ks][3] = *(const u32*)(g_ql + r1 + ks * 16 + 8);
        }
    }

    const bf16* sgbase = g_sig + (size_t)h * NS * SD;
    {
        int e0 = tid, e1 = tid + 256;
        cp16(&SIG[0][e0 >> 3][(e0 & 7) * 8], sgbase + (size_t)(e0 >> 3) * SD + (e0 & 7) * 8);
        cp16(&SIG[0][e1 >> 3][(e1 & 7) * 8], sgbase + (size_t)(e1 >> 3) * SD + (e1 & 7) * 8);
        cp_commit();
    }

    // ldmatrix base address for this thread: row = tn*32 + (lane&7), matrix = lane>>3
    u32 lmbase = (u32)__cvta_generic_to_shared(
        &SIG[0][tn * 32 + (lane & 7)][(lane >> 3) * 16]);

    float k1[2] = {-__int_as_float(0x7f800000), -__int_as_float(0x7f800000)};
    float k2[2] = {k1[0], k1[1]};

#define UPD(r, s, ci) do {                                             \
        u32 _kb = (__float_as_uint(s) & 0xFFFFFC00u) | (u32)(ci);      \
        float _kf = __uint_as_float(_kb);                              \
        float _m = fminf(k1[r], _kf);                                  \
        k1[r] = fmaxf(k1[r], _kf);                                     \
        k2[r] = fmaxf(k2[r], _m);                                      \
    } while (0)

    for (int c = 0; c < 16; c++) {
        int buf = c & 1;
        cp_wait0();
        __syncthreads();
        if (c < 15) {
            const bf16* src = sgbase + (size_t)(c + 1) * 64 * SD;
            int e0 = tid, e1 = tid + 256;
            cp16(&SIG[buf ^ 1][e0 >> 3][(e0 & 7) * 8], src + (size_t)(e0 >> 3) * SD + (e0 & 7) * 8);
            cp16(&SIG[buf ^ 1][e1 >> 3][(e1 & 7) * 8], src + (size_t)(e1 >> 3) * SD + (e1 & 7) * 8);
            cp_commit();
        }
        u32 lmc = lmbase + (u32)buf * (64 * SLDS * 2);
        int cbase = c * 64 + tn * 32 + tig * 2;
#pragma unroll
        for (int nt = 0; nt < 4; nt++) {
            u32 b0[4], b1[4];
            ldsm_x4(b0[0], b0[1], b0[2], b0[3], lmc + nt * (8 * SLDS * 2));
            ldsm_x4(b1[0], b1[1], b1[2], b1[3], lmc + nt * (8 * SLDS * 2) + 16);
            float c0 = 0.f, c1 = 0.f, c2 = 0.f, c3 = 0.f;
#pragma unroll
            for (int ks = 0; ks < 4; ks++) {
                mma_bf16(c0, c1, c2, c3, ah[ks][0], ah[ks][1], ah[ks][2], ah[ks][3],
                         b0[ks], b1[ks]);
                mma_bf16(c0, c1, c2, c3, al[ks][0], al[ks][1], al[ks][2], al[ks][3],
                         b0[ks], b1[ks]);
            }
            int ci0 = 1023 - (cbase + nt * 8);
            UPD(0, c0, ci0); UPD(0, c1, ci0 - 1);
            UPD(1, c2, ci0); UPD(1, c3, ci0 - 1);
        }
    }

    // merge top-2 across the 4 lanes sharing each row (tig axis)
#pragma unroll
    for (int off = 1; off < 4; off <<= 1) {
#pragma unroll
        for (int r = 0; r < 2; r++) {
            float ok1 = __shfl_xor_sync(0xffffffffu, k1[r], off);
            float ok2 = __shfl_xor_sync(0xffffffffu, k2[r], off);
            float m = fminf(k1[r], ok1);
            k1[r] = fmaxf(k1[r], ok1);
            k2[r] = fmaxf(fmaxf(k2[r], ok2), m);
        }
    }
    if (tig == 0) {
        int r = tm * 16 + gid;
        Mk1[tn][r] = k1[0]; Mk2[tn][r] = k2[0];
        Mk1[tn][r + 8] = k1[1]; Mk2[tn][r + 8] = k2[1];
    }
    __syncthreads();

    if (tid < 64) {
        float a1 = Mk1[0][tid], a2 = Mk2[0][tid];
        float b1 = Mk1[1][tid], b2 = Mk2[1][tid];
        float m = fminf(a1, b1);
        float K1 = fmaxf(a1, b1);
        float K2 = fmaxf(fmaxf(a2, b2), m);
        u32 kb1 = __float_as_uint(K1), kb2 = __float_as_uint(K2);
        int I1 = 1023 - (int)(kb1 & 1023u);
        int I2 = 1023 - (int)(kb2 & 1023u);
        float V1 = __uint_as_float(kb1 & 0xFFFFFC00u);
        float V2 = __uint_as_float(kb2 & 0xFFFFFC00u);
        float t = temp[0];
        float inv = 1.0f / (t * 8.0f);           // 1/(temperature*sqrt(64))
        float e = expf((V2 - V1) * inv);
        float w1 = 1.0f / (1.0f + e);
        w1s[tid] = w1;
        w2s[tid] = 1.0f - w1;
        i1s[tid] = I1;
        i2s[tid] = I2;
    }
    __syncthreads();

    {   // gather slot values, blend, write bf16 read
        int tt = tid >> 2, p = tid & 3;
        const float* V = vals + (size_t)h * NS * SD;
        const float4* r1 = (const float4*)(V + (size_t)i1s[tt] * SD);
        const float4* r2 = (const float4*)(V + (size_t)i2s[tt] * SD);
        float a = w1s[tt], b = w2s[tt];
        bf16* dst = g_read + (size_t)(m0 + tt) * DM + h * SD + p * 16;
#pragma unroll
        for (int j = 0; j < 4; j++) {
            float4 xa = r1[p * 4 + j], xb = r2[p * 4 + j];
            float f0 = a * xa.x + b * xb.x;
            float f1 = a * xa.y + b * xb.y;
            float f2 = a * xa.z + b * xb.z;
            float f3 = a * xa.w + b * xb.w;
            ((__nv_bfloat162*)(dst + j * 4))[0] = __floats2bfloat162_rn(f0, f1);
            ((__nv_bfloat162*)(dst + j * 4))[1] = __floats2bfloat162_rn(f2, f3);
        }
    }
}

// ---------------- out projection (R6: 128x64, 2-stage) ----------------------
__global__ void __launch_bounds__(256) gemm_out(const float* __restrict__ ob,
                                                const float* __restrict__ x,
                                                float* __restrict__ out) {
    __shared__ __align__(16) bf16 As[2][128 * 40];
    __shared__ __align__(16) bf16 Ws[2][64 * 40];
    __shared__ __align__(16) float Cs[8 * 16 * 20];

    int tid = threadIdx.x, warp = tid >> 5, lane = tid & 31;
    int m0 = blockIdx.y * 128, n0 = blockIdx.x * 64;
    int wm = warp & 3, wn = warp >> 2;

    wmma::fragment<wmma::accumulator, 16, 16, 16, float> acc[2][2];
#pragma unroll
    for (int i = 0; i < 2; i++)
#pragma unroll
        for (int j = 0; j < 2; j++) wmma::fill_fragment(acc[i][j], 0.0f);

    int rA0 = tid >> 2, rA1 = (tid + 256) >> 2, vA = tid & 3;
#define GO_STAGE(s, kb) do {                                                   \
        size_t a0 = (size_t)(m0 + rA0) * DM + (kb) + vA * 8;                   \
        size_t a1 = (size_t)(m0 + rA1) * DM + (kb) + vA * 8;                   \
        cp16(&As[s][rA0 * 40 + vA * 8], g_read + a0);                          \
        cp16(&As[s][rA1 * 40 + vA * 8], g_read + a1);                          \
        size_t w0 = (size_t)(n0 + rA0) * DM + (kb) + vA * 8;                   \
        cp16(&Ws[s][rA0 * 40 + vA * 8], g_wo + w0);                            \
    } while (0)

    GO_STAGE(0, 0);
    cp_commit();

    for (int kt = 0; kt < 32; kt++) {
        int buf = kt & 1;
        cp_wait0();
        __syncthreads();
        if (kt < 31) {
            GO_STAGE(buf ^ 1, (kt + 1) * 32);
            cp_commit();
        }
#pragma unroll
        for (int ks = 0; ks < 2; ks++) {
            wmma::fragment<wmma::matrix_a, 16, 16, 16, bf16, wmma::row_major> af[2];
            wmma::fragment<wmma::matrix_b, 16, 16, 16, bf16, wmma::col_major> bf_[2];
#pragma unroll
            for (int i = 0; i < 2; i++)
                wmma::load_matrix_sync(af[i], &As[buf][(wm * 32 + i * 16) * 40 + ks * 16], 40);
#pragma unroll
            for (int j = 0; j < 2; j++)
                wmma::load_matrix_sync(bf_[j], &Ws[buf][(wn * 32 + j * 16) * 40 + ks * 16], 40);
#pragma unroll
            for (int i = 0; i < 2; i++)
#pragma unroll
                for (int j = 0; j < 2; j++)
                    wmma::mma_sync(acc[i][j], af[i], bf_[j], acc[i][j]);
        }
    }
    __syncthreads();
    float* cs = Cs + warp * (16 * 20);
#pragma unroll
    for (int i = 0; i < 2; i++)
#pragma unroll
        for (int j = 0; j < 2; j++) {
            wmma::store_matrix_sync(cs, acc[i][j], 20, wmma::mem_row_major);
            __syncwarp();
            int mb = m0 + wm * 32 + i * 16, nb = n0 + wn * 32 + j * 16;
#pragma unroll
            for (int t = 0; t < 8; t++) {
                int e = t * 32 + lane;
                int r = e >> 4, c = e & 15;
                size_t o = (size_t)(mb + r) * DM + nb + c;
                out[o] = cs[r * 20 + c] + ob[nb + c] + x[o];
            }
            __syncwarp();
        }
}

// ---------------- launch ----------------------------------------------------
extern "C" void kernel_launch(void* const* d_in, const int* in_sizes, int n_in,
                              void* d_out, int out_size) {
    const float* x = (const float*)d_in[0];
    const float* gamma = (const float*)d_in[1];
    const float* beta = (const float*)d_in[2];
    const float* qw = (const float*)d_in[3];
    const float* qb = (const float*)d_in[4];
    const float* sig = (const float*)d_in[5];
    const float* vals = (const float*)d_in[6];
    const float* ow = (const float*)d_in[7];
    const float* ob = (const float*)d_in[8];
    const float* temp = (const float*)d_in[9];
    float* out = (float*)d_out;

    cudaFuncSetAttribute(gemm_qproj, cudaFuncAttributeMaxDynamicSharedMemorySize, QP_SMEM);

    convert_kernel<<<(3 * DM * DM) / 256, 256>>>(qw, ow, sig);
    ln_kernel<<<TOKENS, 256>>>(x, gamma, beta);
    gemm_qproj<<<dim3(DM / 64, TOKENS / 128), 256, QP_SMEM>>>(qb);
    scores_kernel<<<dim3(TOKENS / 64, NH), 256>>>(vals, temp);
    gemm_out<<<dim3(DM / 64, TOKENS / 128), 256>>>(ob, x, out);
}

// round 17
// speedup vs baseline: 1.6743x; 1.4132x over previous
#include <cuda_runtime.h>
#include <cuda.h>
#include <cuda_bf16.h>
#include <cstdint>

typedef __nv_bfloat16 bf16;
typedef unsigned int u32;
typedef unsigned long long u64;

#define TOKENS 8192
#define DM 1024
#define NH 16
#define SD 64
#define NS 1024

// ---------------- scratch (static __device__, no allocation) ----------------
__device__ __align__(1024) bf16 g_xh[TOKENS * DM];     // x_norm hi
__device__ __align__(1024) bf16 g_xl[TOKENS * DM];     // x_norm lo
__device__ __align__(1024) bf16 g_qh[TOKENS * DM];     // q hi
__device__ __align__(1024) bf16 g_ql[TOKENS * DM];     // q lo
__device__ __align__(1024) bf16 g_read[TOKENS * DM];   // routed read (bf16)
__device__ __align__(1024) bf16 g_wqh[DM * DM];        // q_w hi
__device__ __align__(1024) bf16 g_wql[DM * DM];        // q_w lo
__device__ __align__(1024) bf16 g_wo[DM * DM];         // out_w (plain bf16)
__device__ __align__(1024) bf16 g_sig[NH * NS * SD];   // ternarized signatures

// ---------------- generic helpers -------------------------------------------
__device__ __forceinline__ void cp16(void* s, const void* g) {
    asm volatile("cp.async.cg.shared.global [%0], [%1], 16;\n"
                 :: "r"((u32)__cvta_generic_to_shared(s)), "l"(g));
}
__device__ __forceinline__ void cp_commit() { asm volatile("cp.async.commit_group;\n"); }
__device__ __forceinline__ void cp_wait0() { asm volatile("cp.async.wait_group 0;\n"); }

__device__ __forceinline__ void mma_bf16(float& c0, float& c1, float& c2, float& c3,
                                         u32 a0, u32 a1, u32 a2, u32 a3,
                                         u32 b0, u32 b1) {
    asm volatile(
        "mma.sync.aligned.m16n8k16.row.col.f32.bf16.bf16.f32 "
        "{%0,%1,%2,%3}, {%4,%5,%6,%7}, {%8,%9}, {%0,%1,%2,%3};\n"
        : "+f"(c0), "+f"(c1), "+f"(c2), "+f"(c3)
        : "r"(a0), "r"(a1), "r"(a2), "r"(a3), "r"(b0), "r"(b1));
}

__device__ __forceinline__ void ldsm_x4(u32& r0, u32& r1, u32& r2, u32& r3, u32 saddr) {
    asm volatile("ldmatrix.sync.aligned.m8n8.x4.shared.b16 {%0,%1,%2,%3}, [%4];\n"
                 : "=r"(r0), "=r"(r1), "=r"(r2), "=r"(r3) : "r"(saddr));
}

// SW128 swizzle for 128B-wide rows (verified vs TMA SWIZZLE_128B in test_tma.cu)
__device__ __forceinline__ u32 swz(u32 o) { return o ^ ((o >> 3) & 0x70); }

// ---------------- TMA / mbarrier helpers ------------------------------------
__device__ __forceinline__ void mbar_init(u32 mbar, u32 count) {
    asm volatile("mbarrier.init.shared.b64 [%0], %1;" :: "r"(mbar), "r"(count) : "memory");
}
__device__ __forceinline__ void mbar_expect(u32 mbar, u32 bytes) {
    asm volatile("mbarrier.arrive.expect_tx.shared.b64 _, [%0], %1;"
                 :: "r"(mbar), "r"(bytes) : "memory");
}
__device__ __forceinline__ void mbar_wait(u32 mbar, u32 parity) {
    u32 done;
    do {
        asm volatile(
            "{\n\t.reg .pred p;\n\t"
            "mbarrier.try_wait.parity.acquire.cta.shared::cta.b64 p, [%1], %2, 0x989680;\n\t"
            "selp.b32 %0, 1, 0, p;\n\t}"
            : "=r"(done) : "r"(mbar), "r"(parity) : "memory");
    } while (!done);
}
__device__ __forceinline__ void tma2d(u32 smem, const CUtensorMap* tm, int cx, int cy, u32 mbar) {
    asm volatile(
        "cp.async.bulk.tensor.2d.shared::cta.global.tile.mbarrier::complete_tx::bytes "
        "[%0], [%1, {%2, %3}], [%4];"
        :: "r"(smem), "l"(tm), "r"(cx), "r"(cy), "r"(mbar) : "memory");
}

// ---------------- convert weights / ternarize signatures --------------------
__global__ void __launch_bounds__(256) convert_kernel(const float* __restrict__ qw,
                                                      const float* __restrict__ ow,
                                                      const float* __restrict__ sig) {
    int i = blockIdx.x * 256 + threadIdx.x;
    const int N = DM * DM;
    if (i < N) {
        float w = qw[i];
        bf16 h = __float2bfloat16(w);
        g_wqh[i] = h;
        g_wql[i] = __float2bfloat16(w - __bfloat162float(h));
    } else if (i < 2 * N) {
        g_wo[i - N] = __float2bfloat16(ow[i - N]);
    } else if (i < 2 * N + NH * NS * SD) {
        float s = sig[i - 2 * N];
        float t = (s > 0.3f) ? 1.0f : ((s < -0.3f) ? -1.0f : 0.0f);
        g_sig[i - 2 * N] = __float2bfloat16(t);
    }
}

// ---------------- layernorm with hi/lo split output -------------------------
__global__ void __launch_bounds__(256) ln_kernel(const float* __restrict__ x,
                                                 const float* __restrict__ gamma,
                                                 const float* __restrict__ beta) {
    int m = blockIdx.x;
    int tid = threadIdx.x;
    const float4 v = reinterpret_cast<const float4*>(x + (size_t)m * DM)[tid];
    float s = v.x + v.y + v.z + v.w;
    float q = v.x * v.x + v.y * v.y + v.z * v.z + v.w * v.w;
#pragma unroll
    for (int o = 16; o; o >>= 1) {
        s += __shfl_xor_sync(0xffffffffu, s, o);
        q += __shfl_xor_sync(0xffffffffu, q, o);
    }
    __shared__ float ss[8], qq[8];
    int w = tid >> 5;
    if ((tid & 31) == 0) { ss[w] = s; qq[w] = q; }
    __syncthreads();
    if (tid == 0) {
        float S = 0.f, Q = 0.f;
        for (int i = 0; i < 8; i++) { S += ss[i]; Q += qq[i]; }
        ss[0] = S; qq[0] = Q;
    }
    __syncthreads();
    float mean = ss[0] * (1.0f / DM);
    float var = qq[0] * (1.0f / DM) - mean * mean;
    float r = rsqrtf(var + 1e-5f);
    const float4 g = reinterpret_cast<const float4*>(gamma)[tid];
    const float4 b = reinterpret_cast<const float4*>(beta)[tid];
    float o0 = (v.x - mean) * r * g.x + b.x;
    float o1 = (v.y - mean) * r * g.y + b.y;
    float o2 = (v.z - mean) * r * g.z + b.z;
    float o3 = (v.w - mean) * r * g.w + b.w;
    size_t base = (size_t)m * DM + tid * 4;
    float oo[4] = {o0, o1, o2, o3};
#pragma unroll
    for (int i = 0; i < 4; i++) {
        bf16 h = __float2bfloat16(oo[i]);
        g_xh[base + i] = h;
        g_xl[base + i] = __float2bfloat16(oo[i] - __bfloat162float(h));
    }
}

// ---------------- q projection: TMA + mma.sync (128x64 tile) ----------------
// stage = Ah 16K + Al 16K + Wh 8K + Wl 8K = 48K; 2 stages + 1K align
#define QP_STRIDE 49152
#define QP_SMEM (2 * QP_STRIDE + 1024)

__global__ void __launch_bounds__(256)
gemm_qproj(const float* __restrict__ qb,
           const __grid_constant__ CUtensorMap tm_ah,
           const __grid_constant__ CUtensorMap tm_al,
           const __grid_constant__ CUtensorMap tm_wh,
           const __grid_constant__ CUtensorMap tm_wl) {
    extern __shared__ char dynq[];
    __shared__ __align__(8) u64 mbars[2];
    __shared__ float sbias[64];

    int tid = threadIdx.x, warp = tid >> 5, lane = tid & 31;
    int wm = warp & 3, wn = warp >> 2;                 // warp tile 32x32
    int n0 = blockIdx.x * 64, m0 = blockIdx.y * 128;

    u32 base = ((u32)__cvta_generic_to_shared(dynq) + 1023u) & ~1023u;
    u32 mb[2] = {(u32)__cvta_generic_to_shared(&mbars[0]),
                 (u32)__cvta_generic_to_shared(&mbars[1])};

    if (tid < 64) sbias[tid] = qb[n0 + tid];
    if (tid == 0) {
        mbar_init(mb[0], 1); mbar_init(mb[1], 1);
        asm volatile("fence.proxy.async.shared::cta;" ::: "memory");
    }
    __syncthreads();

    if (tid == 0) {
#pragma unroll
        for (int p = 0; p < 2; p++) {
            mbar_expect(mb[p], QP_STRIDE);
            int k0 = p * 64;
            u32 st = base + p * QP_STRIDE;
            tma2d(st + 0,     &tm_ah, k0, m0, mb[p]);
            tma2d(st + 16384, &tm_al, k0, m0, mb[p]);
            tma2d(st + 32768, &tm_wh, k0, n0, mb[p]);
            tma2d(st + 40960, &tm_wl, k0, n0, mb[p]);
        }
    }

    float acc[2][4][4];
#pragma unroll
    for (int i = 0; i < 2; i++)
#pragma unroll
        for (int j = 0; j < 4; j++)
#pragma unroll
            for (int e = 0; e < 4; e++) acc[i][j][e] = 0.0f;

    for (int kt = 0; kt < 16; kt++) {
        int buf = kt & 1;
        u32 par = (u32)((kt >> 1) & 1);
        mbar_wait(mb[buf], par);
        u32 Ab = base + buf * QP_STRIDE;
        u32 Lb = Ab + 16384, Wb = Ab + 32768, Vb = Ab + 40960;
#pragma unroll
        for (int kp = 0; kp < 2; kp++) {
            // W fragments: 4 n-groups x (b0,b1 for 2 ks), hi+lo
            u32 wh[4][4], wl[4][4];
#pragma unroll
            for (int g = 0; g < 4; g++) {
                u32 wo = swz((u32)((wn * 32 + g * 8 + (lane & 7)) * 128 +
                                   kp * 64 + (lane >> 3) * 16));
                ldsm_x4(wh[g][0], wh[g][1], wh[g][2], wh[g][3], Wb + wo);
                ldsm_x4(wl[g][0], wl[g][1], wl[g][2], wl[g][3], Vb + wo);
            }
#pragma unroll
            for (int mt = 0; mt < 2; mt++) {
#pragma unroll
                for (int kse = 0; kse < 2; kse++) {
                    int ks = kp * 2 + kse;
                    u32 ao = swz((u32)((wm * 32 + mt * 16 + (lane & 15)) * 128 +
                                       ks * 32 + (lane >> 4) * 16));
                    u32 a0, a1, a2, a3, l0, l1, l2, l3;
                    ldsm_x4(a0, a1, a2, a3, Ab + ao);
                    ldsm_x4(l0, l1, l2, l3, Lb + ao);
#pragma unroll
                    for (int g = 0; g < 4; g++) {
                        mma_bf16(acc[mt][g][0], acc[mt][g][1], acc[mt][g][2], acc[mt][g][3],
                                 a0, a1, a2, a3, wh[g][kse * 2], wh[g][kse * 2 + 1]);
                        mma_bf16(acc[mt][g][0], acc[mt][g][1], acc[mt][g][2], acc[mt][g][3],
                                 a0, a1, a2, a3, wl[g][kse * 2], wl[g][kse * 2 + 1]);
                        mma_bf16(acc[mt][g][0], acc[mt][g][1], acc[mt][g][2], acc[mt][g][3],
                                 l0, l1, l2, l3, wh[g][kse * 2], wh[g][kse * 2 + 1]);
                    }
                }
            }
        }
        __syncthreads();                 // all reads of buf done
        if (tid == 0 && kt + 2 < 16) {
            mbar_expect(mb[buf], QP_STRIDE);
            int k0 = (kt + 2) * 64;
            u32 st = base + buf * QP_STRIDE;
            tma2d(st + 0,     &tm_ah, k0, m0, mb[buf]);
            tma2d(st + 16384, &tm_al, k0, m0, mb[buf]);
            tma2d(st + 32768, &tm_wh, k0, n0, mb[buf]);
            tma2d(st + 40960, &tm_wl, k0, n0, mb[buf]);
        }
    }

    // epilogue: acc + bias -> (hi, lo) bf16 pairs, direct from fragments
    int rr = m0 + wm * 32 + (lane >> 2);
    int cc = 2 * (lane & 3);
#pragma unroll
    for (int mt = 0; mt < 2; mt++) {
#pragma unroll
        for (int g = 0; g < 4; g++) {
            int sb = wn * 32 + g * 8 + cc;
            int col = n0 + sb;
            float b0 = sbias[sb], b1 = sbias[sb + 1];
            float v0 = acc[mt][g][0] + b0, v1 = acc[mt][g][1] + b1;
            float v2 = acc[mt][g][2] + b0, v3 = acc[mt][g][3] + b1;
            size_t o0 = (size_t)(rr + mt * 16) * DM + col;
            size_t o1 = o0 + 8 * DM;
            __nv_bfloat162 hp, lp;
            hp.x = __float2bfloat16(v0); hp.y = __float2bfloat16(v1);
            lp.x = __float2bfloat16(v0 - __bfloat162float(hp.x));
            lp.y = __float2bfloat16(v1 - __bfloat162float(hp.y));
            *(__nv_bfloat162*)(g_qh + o0) = hp;
            *(__nv_bfloat162*)(g_ql + o0) = lp;
            hp.x = __float2bfloat16(v2); hp.y = __float2bfloat16(v3);
            lp.x = __float2bfloat16(v2 - __bfloat162float(hp.x));
            lp.y = __float2bfloat16(v3 - __bfloat162float(hp.y));
            *(__nv_bfloat162*)(g_qh + o1) = hp;
            *(__nv_bfloat162*)(g_ql + o1) = lp;
        }
    }
}

// ---------------- out projection: TMA + mma.sync (128x64 tile) --------------
#define GO_STRIDE 24576
#define GO_SMEM (2 * GO_STRIDE + 1024)

__global__ void __launch_bounds__(256)
gemm_out(const float* __restrict__ ob,
         const float* __restrict__ x,
         float* __restrict__ out,
         const __grid_constant__ CUtensorMap tm_a,
         const __grid_constant__ CUtensorMap tm_w) {
    extern __shared__ char dyno[];
    __shared__ __align__(8) u64 mbars[2];
    __shared__ float sbias[64];

    int tid = threadIdx.x, warp = tid >> 5, lane = tid & 31;
    int wm = warp & 3, wn = warp >> 2;
    int n0 = blockIdx.x * 64, m0 = blockIdx.y * 128;

    u32 base = ((u32)__cvta_generic_to_shared(dyno) + 1023u) & ~1023u;
    u32 mb[2] = {(u32)__cvta_generic_to_shared(&mbars[0]),
                 (u32)__cvta_generic_to_shared(&mbars[1])};

    if (tid < 64) sbias[tid] = ob[n0 + tid];
    if (tid == 0) {
        mbar_init(mb[0], 1); mbar_init(mb[1], 1);
        asm volatile("fence.proxy.async.shared::cta;" ::: "memory");
    }
    __syncthreads();

    if (tid == 0) {
#pragma unroll
        for (int p = 0; p < 2; p++) {
            mbar_expect(mb[p], GO_STRIDE);
            int k0 = p * 64;
            u32 st = base + p * GO_STRIDE;
            tma2d(st + 0,     &tm_a, k0, m0, mb[p]);
            tma2d(st + 16384, &tm_w, k0, n0, mb[p]);
        }
    }

    float acc[2][4][4];
#pragma unroll
    for (int i = 0; i < 2; i++)
#pragma unroll
        for (int j = 0; j < 4; j++)
#pragma unroll
            for (int e = 0; e < 4; e++) acc[i][j][e] = 0.0f;

    for (int kt = 0; kt < 16; kt++) {
        int buf = kt & 1;
        u32 par = (u32)((kt >> 1) & 1);
        mbar_wait(mb[buf], par);
        u32 Ab = base + buf * GO_STRIDE;
        u32 Wb = Ab + 16384;
#pragma unroll
        for (int kp = 0; kp < 2; kp++) {
            u32 wf[4][4];
#pragma unroll
            for (int g = 0; g < 4; g++) {
                u32 wo = swz((u32)((wn * 32 + g * 8 + (lane & 7)) * 128 +
                                   kp * 64 + (lane >> 3) * 16));
                ldsm_x4(wf[g][0], wf[g][1], wf[g][2], wf[g][3], Wb + wo);
            }
#pragma unroll
            for (int mt = 0; mt < 2; mt++) {
#pragma unroll
                for (int kse = 0; kse < 2; kse++) {
                    int ks = kp * 2 + kse;
                    u32 ao = swz((u32)((wm * 32 + mt * 16 + (lane & 15)) * 128 +
                                       ks * 32 + (lane >> 4) * 16));
                    u32 a0, a1, a2, a3;
                    ldsm_x4(a0, a1, a2, a3, Ab + ao);
#pragma unroll
                    for (int g = 0; g < 4; g++)
                        mma_bf16(acc[mt][g][0], acc[mt][g][1], acc[mt][g][2], acc[mt][g][3],
                                 a0, a1, a2, a3, wf[g][kse * 2], wf[g][kse * 2 + 1]);
                }
            }
        }
        __syncthreads();
        if (tid == 0 && kt + 2 < 16) {
            mbar_expect(mb[buf], GO_STRIDE);
            int k0 = (kt + 2) * 64;
            u32 st = base + buf * GO_STRIDE;
            tma2d(st + 0,     &tm_a, k0, m0, mb[buf]);
            tma2d(st + 16384, &tm_w, k0, n0, mb[buf]);
        }
    }

    int rr = m0 + wm * 32 + (lane >> 2);
    int cc = 2 * (lane & 3);
#pragma unroll
    for (int mt = 0; mt < 2; mt++) {
#pragma unroll
        for (int g = 0; g < 4; g++) {
            int sb = wn * 32 + g * 8 + cc;
            int col = n0 + sb;
            float b0 = sbias[sb], b1 = sbias[sb + 1];
            size_t o0 = (size_t)(rr + mt * 16) * DM + col;
            size_t o1 = o0 + 8 * DM;
            float2 x0 = *(const float2*)(x + o0);
            float2 x1 = *(const float2*)(x + o1);
            float2 r0, r1;
            r0.x = acc[mt][g][0] + b0 + x0.x;
            r0.y = acc[mt][g][1] + b1 + x0.y;
            r1.x = acc[mt][g][2] + b0 + x1.x;
            r1.y = acc[mt][g][3] + b1 + x1.y;
            *(float2*)(out + o0) = r0;
            *(float2*)(out + o1) = r1;
        }
    }
}

// ---------------- fused scores + top-2 + softmax + gather (R9 best) ---------
#define SLDS 72

__global__ void __launch_bounds__(256) scores_kernel(const float* __restrict__ vals,
                                                     const float* __restrict__ temp) {
    __shared__ __align__(16) bf16 SIG[2][64][SLDS];
    __shared__ float Mk1[2][64], Mk2[2][64];
    __shared__ float w1s[64], w2s[64];
    __shared__ int i1s[64], i2s[64];

    int tid = threadIdx.x, lane = tid & 31, warp = tid >> 5;
    int tm = warp & 3, tn = warp >> 2;
    int m0 = blockIdx.x * 64, h = blockIdx.y;
    int gid = lane >> 2, tig = lane & 3;

    u32 ah[4][4], al[4][4];
    {
        size_t r0 = (size_t)(m0 + tm * 16 + gid) * DM + h * SD + tig * 2;
        size_t r1 = r0 + 8 * DM;
#pragma unroll
        for (int ks = 0; ks < 4; ks++) {
            ah[ks][0] = *(const u32*)(g_qh + r0 + ks * 16);
            ah[ks][1] = *(const u32*)(g_qh + r1 + ks * 16);
            ah[ks][2] = *(const u32*)(g_qh + r0 + ks * 16 + 8);
            ah[ks][3] = *(const u32*)(g_qh + r1 + ks * 16 + 8);
            al[ks][0] = *(const u32*)(g_ql + r0 + ks * 16);
            al[ks][1] = *(const u32*)(g_ql + r1 + ks * 16);
            al[ks][2] = *(const u32*)(g_ql + r0 + ks * 16 + 8);
            al[ks][3] = *(const u32*)(g_ql + r1 + ks * 16 + 8);
        }
    }

    const bf16* sgbase = g_sig + (size_t)h * NS * SD;
    {
        int e0 = tid, e1 = tid + 256;
        cp16(&SIG[0][e0 >> 3][(e0 & 7) * 8], sgbase + (size_t)(e0 >> 3) * SD + (e0 & 7) * 8);
        cp16(&SIG[0][e1 >> 3][(e1 & 7) * 8], sgbase + (size_t)(e1 >> 3) * SD + (e1 & 7) * 8);
        cp_commit();
    }

    u32 lmbase = (u32)__cvta_generic_to_shared(
        &SIG[0][tn * 32 + (lane & 7)][(lane >> 3) * 16]);

    float k1[2] = {-__int_as_float(0x7f800000), -__int_as_float(0x7f800000)};
    float k2[2] = {k1[0], k1[1]};

#define UPD(r, s, ci) do {                                             \
        u32 _kb = (__float_as_uint(s) & 0xFFFFFC00u) | (u32)(ci);      \
        float _kf = __uint_as_float(_kb);                              \
        float _m = fminf(k1[r], _kf);                                  \
        k1[r] = fmaxf(k1[r], _kf);                                     \
        k2[r] = fmaxf(k2[r], _m);                                      \
    } while (0)

    for (int c = 0; c < 16; c++) {
        int buf = c & 1;
        cp_wait0();
        __syncthreads();
        if (c < 15) {
            const bf16* src = sgbase + (size_t)(c + 1) * 64 * SD;
            int e0 = tid, e1 = tid + 256;
            cp16(&SIG[buf ^ 1][e0 >> 3][(e0 & 7) * 8], src + (size_t)(e0 >> 3) * SD + (e0 & 7) * 8);
            cp16(&SIG[buf ^ 1][e1 >> 3][(e1 & 7) * 8], src + (size_t)(e1 >> 3) * SD + (e1 & 7) * 8);
            cp_commit();
        }
        u32 lmc = lmbase + (u32)buf * (64 * SLDS * 2);
        int cbase = c * 64 + tn * 32 + tig * 2;
#pragma unroll
        for (int nt = 0; nt < 4; nt++) {
            u32 b0[4], b1[4];
            ldsm_x4(b0[0], b0[1], b0[2], b0[3], lmc + nt * (8 * SLDS * 2));
            ldsm_x4(b1[0], b1[1], b1[2], b1[3], lmc + nt * (8 * SLDS * 2) + 16);
            float c0 = 0.f, c1 = 0.f, c2 = 0.f, c3 = 0.f;
#pragma unroll
            for (int ks = 0; ks < 4; ks++) {
                mma_bf16(c0, c1, c2, c3, ah[ks][0], ah[ks][1], ah[ks][2], ah[ks][3],
                         b0[ks], b1[ks]);
                mma_bf16(c0, c1, c2, c3, al[ks][0], al[ks][1], al[ks][2], al[ks][3],
                         b0[ks], b1[ks]);
            }
            int ci0 = 1023 - (cbase + nt * 8);
            UPD(0, c0, ci0); UPD(0, c1, ci0 - 1);
            UPD(1, c2, ci0); UPD(1, c3, ci0 - 1);
        }
    }

#pragma unroll
    for (int off = 1; off < 4; off <<= 1) {
#pragma unroll
        for (int r = 0; r < 2; r++) {
            float ok1 = __shfl_xor_sync(0xffffffffu, k1[r], off);
            float ok2 = __shfl_xor_sync(0xffffffffu, k2[r], off);
            float m = fminf(k1[r], ok1);
            k1[r] = fmaxf(k1[r], ok1);
            k2[r] = fmaxf(fmaxf(k2[r], ok2), m);
        }
    }
    if (tig == 0) {
        int r = tm * 16 + gid;
        Mk1[tn][r] = k1[0]; Mk2[tn][r] = k2[0];
        Mk1[tn][r + 8] = k1[1]; Mk2[tn][r + 8] = k2[1];
    }
    __syncthreads();

    if (tid < 64) {
        float a1 = Mk1[0][tid], a2 = Mk2[0][tid];
        float b1 = Mk1[1][tid], b2 = Mk2[1][tid];
        float m = fminf(a1, b1);
        float K1 = fmaxf(a1, b1);
        float K2 = fmaxf(fmaxf(a2, b2), m);
        u32 kb1 = __float_as_uint(K1), kb2 = __float_as_uint(K2);
        int I1 = 1023 - (int)(kb1 & 1023u);
        int I2 = 1023 - (int)(kb2 & 1023u);
        float V1 = __uint_as_float(kb1 & 0xFFFFFC00u);
        float V2 = __uint_as_float(kb2 & 0xFFFFFC00u);
        float t = temp[0];
        float inv = 1.0f / (t * 8.0f);
        float e = expf((V2 - V1) * inv);
        float w1 = 1.0f / (1.0f + e);
        w1s[tid] = w1;
        w2s[tid] = 1.0f - w1;
        i1s[tid] = I1;
        i2s[tid] = I2;
    }
    __syncthreads();

    {
        int tt = tid >> 2, p = tid & 3;
        const float* V = vals + (size_t)h * NS * SD;
        const float4* r1 = (const float4*)(V + (size_t)i1s[tt] * SD);
        const float4* r2 = (const float4*)(V + (size_t)i2s[tt] * SD);
        float a = w1s[tt], b = w2s[tt];
        bf16* dst = g_read + (size_t)(m0 + tt) * DM + h * SD + p * 16;
#pragma unroll
        for (int j = 0; j < 4; j++) {
            float4 xa = r1[p * 4 + j], xb = r2[p * 4 + j];
            float f0 = a * xa.x + b * xb.x;
            float f1 = a * xa.y + b * xb.y;
            float f2 = a * xa.z + b * xb.z;
            float f3 = a * xa.w + b * xb.w;
            ((__nv_bfloat162*)(dst + j * 4))[0] = __floats2bfloat162_rn(f0, f1);
            ((__nv_bfloat162*)(dst + j * 4))[1] = __floats2bfloat162_rn(f2, f3);
        }
    }
}

// ---------------- host: tensormap encode via runtime-fetched driver API -----
typedef CUresult (*tmap_encode_t)(CUtensorMap*, CUtensorMapDataType, cuuint32_t, void*,
                                  const cuuint64_t*, const cuuint64_t*, const cuuint32_t*,
                                  const cuuint32_t*, CUtensorMapInterleave, CUtensorMapSwizzle,
                                  CUtensorMapL2promotion, CUtensorMapFloatOOBfill);

static tmap_encode_t get_tmap_encode() {
    static tmap_encode_t fn = nullptr;
    if (!fn) {
        void* p = nullptr;
        cudaDriverEntryPointQueryResult st;
#if CUDART_VERSION >= 12050
        cudaGetDriverEntryPointByVersion("cuTensorMapEncodeTiled", &p, 12000,
                                         cudaEnableDefault, &st);
#else
        cudaGetDriverEntryPoint("cuTensorMapEncodeTiled", &p, cudaEnableDefault, &st);
#endif
        fn = (tmap_encode_t)p;
    }
    return fn;
}

static void make_map2d(CUtensorMap* tm, void* g, unsigned long long d0,
                       unsigned long long d1, unsigned boxh) {
    cuuint64_t dims[2] = {d0, d1};
    cuuint64_t str[1] = {d0 * 2};              // bf16 row pitch in bytes
    cuuint32_t box[2] = {64, boxh};            // 128B x boxh rows (SW128)
    cuuint32_t es[2] = {1, 1};
    get_tmap_encode()(tm, CU_TENSOR_MAP_DATA_TYPE_BFLOAT16, 2, g, dims, str, box, es,
                      CU_TENSOR_MAP_INTERLEAVE_NONE, CU_TENSOR_MAP_SWIZZLE_128B,
                      CU_TENSOR_MAP_L2_PROMOTION_L2_128B, CU_TENSOR_MAP_FLOAT_OOB_FILL_NONE);
}

// ---------------- launch ----------------------------------------------------
extern "C" void kernel_launch(void* const* d_in, const int* in_sizes, int n_in,
                              void* d_out, int out_size) {
    const float* x = (const float*)d_in[0];
    const float* gamma = (const float*)d_in[1];
    const float* beta = (const float*)d_in[2];
    const float* qw = (const float*)d_in[3];
    const float* qb = (const float*)d_in[4];
    const float* sig = (const float*)d_in[5];
    const float* vals = (const float*)d_in[6];
    const float* ow = (const float*)d_in[7];
    const float* ob = (const float*)d_in[8];
    const float* temp = (const float*)d_in[9];
    float* out = (float*)d_out;

    void *pxh, *pxl, *pwh, *pwl, *prd, *pwo;
    cudaGetSymbolAddress(&pxh, g_xh);
    cudaGetSymbolAddress(&pxl, g_xl);
    cudaGetSymbolAddress(&pwh, g_wqh);
    cudaGetSymbolAddress(&pwl, g_wql);
    cudaGetSymbolAddress(&prd, g_read);
    cudaGetSymbolAddress(&pwo, g_wo);

    static CUtensorMap tm_ah, tm_al, tm_wh, tm_wl, tm_rd, tm_wo;
    make_map2d(&tm_ah, pxh, DM, TOKENS, 128);
    make_map2d(&tm_al, pxl, DM, TOKENS, 128);
    make_map2d(&tm_wh, pwh, DM, DM, 64);
    make_map2d(&tm_wl, pwl, DM, DM, 64);
    make_map2d(&tm_rd, prd, DM, TOKENS, 128);
    make_map2d(&tm_wo, pwo, DM, DM, 64);

    cudaFuncSetAttribute(gemm_qproj, cudaFuncAttributeMaxDynamicSharedMemorySize, QP_SMEM);
    cudaFuncSetAttribute(gemm_out, cudaFuncAttributeMaxDynamicSharedMemorySize, GO_SMEM);

    convert_kernel<<<(3 * DM * DM) / 256, 256>>>(qw, ow, sig);
    ln_kernel<<<TOKENS, 256>>>(x, gamma, beta);
    gemm_qproj<<<dim3(DM / 64, TOKENS / 128), 256, QP_SMEM>>>(qb, tm_ah, tm_al, tm_wh, tm_wl);
    scores_kernel<<<dim3(TOKENS / 64, NH), 256>>>(vals, temp);
    gemm_out<<<dim3(DM / 64, TOKENS / 128), 256, GO_SMEM>>>(ob, x, out, tm_rd, tm_wo);
}